// round 1
// baseline (speedup 1.0000x reference)
#include <cuda_runtime.h>
#include <math_constants.h>

#define NN  1024
#define VV  32000
#define BB  16
#define TT  128
#define GG  128            // CTAs in forward kernel (all co-resident)
#define RR  (NN/GG)        // 8 rows of E_T per CTA
#define TPB 256

// ---------------- device scratch (static; no runtime alloc) ----------------
__device__ float    d_ET[NN*NN];        // exp(log_T - rowmax), 4 MB
__device__ float    d_rowmax[NN];
__device__ float    d_rowlse[NN];
__device__ float    d_collse[NN];
__device__ float    d_piadj[NN];        // log_pi - rowmax
__device__ float    d_emitg[TT*BB*NN];  // emit + rowmax, layout [t][b][m], 8 MB
__device__ float    d_eag[BB*NN];       // exp(alpha - gmax), layout [b][n]
__device__ unsigned d_gmaxkey[TT*BB];   // keyed-float atomicMax history
__device__ float    d_easum[TT*BB];     // sum_n ea per (t,b) history
__device__ unsigned d_barcnt;           // grid barrier counter

// ---------------- helpers ----------------
__device__ __forceinline__ unsigned fkey(float f) {
    unsigned u = __float_as_uint(f);
    return (u & 0x80000000u) ? ~u : (u | 0x80000000u);
}
__device__ __forceinline__ float funkey(unsigned k) {
    return (k & 0x80000000u) ? __uint_as_float(k & 0x7fffffffu)
                             : __uint_as_float(~k);
}

// monotone-counter grid barrier; caller passes cumulative target
__device__ __forceinline__ void gbar(unsigned target) {
    __syncthreads();
    if (threadIdx.x == 0) {
        __threadfence();                 // order prior writes/atomics (gpu scope)
        atomicAdd(&d_barcnt, 1u);
        while (*((volatile unsigned*)&d_barcnt) < target) __nanosleep(64);
        __threadfence();                 // invalidate L1 so later loads are fresh
    }
    __syncthreads();
}

// ---------------- prep kernels ----------------
// row logsumexp of emission (N rows of V), online per-thread + block tree
__global__ void k_rowlse(const float* __restrict__ emis) {
    int n = blockIdx.x;
    const float* row = emis + (size_t)n * VV;
    float mx = -CUDART_INF_F, s = 0.f;
    for (int i = threadIdx.x; i < VV; i += TPB) {
        float v = row[i];
        if (v > mx) { s = s * __expf(mx - v) + 1.f; mx = v; }
        else        { s += __expf(v - mx); }
    }
    __shared__ float smx[TPB], ss[TPB];
    smx[threadIdx.x] = mx; ss[threadIdx.x] = s;
    __syncthreads();
    for (int off = TPB / 2; off; off >>= 1) {
        if (threadIdx.x < off) {
            float m1 = smx[threadIdx.x], s1 = ss[threadIdx.x];
            float m2 = smx[threadIdx.x + off], s2 = ss[threadIdx.x + off];
            float m = fmaxf(m1, m2);
            ss[threadIdx.x]  = s1 * __expf(m1 - m) + s2 * __expf(m2 - m);
            smx[threadIdx.x] = m;
        }
        __syncthreads();
    }
    if (threadIdx.x == 0) d_rowlse[n] = smx[0] + __logf(ss[0]);
}

// column logsumexp of transition (over dim 0), 32 cols per block, coalesced
__global__ void k_collse(const float* __restrict__ trans) {
    int col = blockIdx.x * 32 + threadIdx.x;   // threadIdx.x in [0,32)
    int ty  = threadIdx.y;                     // [0,8)
    float mx = -CUDART_INF_F, s = 0.f;
    for (int m = ty; m < NN; m += 8) {
        float v = trans[m * NN + col];
        if (v > mx) { s = s * __expf(mx - v) + 1.f; mx = v; }
        else        { s += __expf(v - mx); }
    }
    __shared__ float smx[8][32], ss[8][32];
    smx[ty][threadIdx.x] = mx; ss[ty][threadIdx.x] = s;
    __syncthreads();
    if (ty == 0) {
        float m1 = mx, s1 = s;
        for (int j = 1; j < 8; j++) {
            float m2 = smx[j][threadIdx.x], s2 = ss[j][threadIdx.x];
            float m = fmaxf(m1, m2);
            s1 = s1 * __expf(m1 - m) + s2 * __expf(m2 - m);
            m1 = m;
        }
        d_collse[col] = m1 + __logf(s1);
    }
}

// rowmax of log_T and E_T = exp(log_T - rowmax)
__global__ void k_prepT(const float* __restrict__ trans) {
    int m = blockIdx.x;
    const float* rowp = trans + (size_t)m * NN;
    float mx = -CUDART_INF_F;
    for (int n = threadIdx.x; n < NN; n += TPB)
        mx = fmaxf(mx, rowp[n] - d_collse[n]);
    __shared__ float smx[TPB];
    smx[threadIdx.x] = mx; __syncthreads();
    for (int off = TPB / 2; off; off >>= 1) {
        if (threadIdx.x < off)
            smx[threadIdx.x] = fmaxf(smx[threadIdx.x], smx[threadIdx.x + off]);
        __syncthreads();
    }
    float rm = smx[0];
    if (threadIdx.x == 0) d_rowmax[m] = rm;
    for (int n = threadIdx.x; n < NN; n += TPB)
        d_ET[m * NN + n] = __expf(rowp[n] - d_collse[n] - rm);
}

// zero per-launch state + piadj = log_softmax(priors) - rowmax
__global__ void k_init(const float* __restrict__ pri) {
    int base = blockIdx.x * (TT * BB / 16);   // 128 per block, 16 blocks
    if (threadIdx.x < 128) {
        d_gmaxkey[base + threadIdx.x] = 0u;
        d_easum[base + threadIdx.x]   = 0.f;
    }
    if (blockIdx.x == 0) {
        if (threadIdx.x == 0) d_barcnt = 0u;
        float mx = -CUDART_INF_F, s = 0.f;
        for (int i = threadIdx.x; i < NN; i += TPB) {
            float v = pri[i];
            if (v > mx) { s = s * __expf(mx - v) + 1.f; mx = v; }
            else        { s += __expf(v - mx); }
        }
        __shared__ float smx[TPB], ss[TPB];
        smx[threadIdx.x] = mx; ss[threadIdx.x] = s;
        __syncthreads();
        for (int off = TPB / 2; off; off >>= 1) {
            if (threadIdx.x < off) {
                float m1 = smx[threadIdx.x], s1 = ss[threadIdx.x];
                float m2 = smx[threadIdx.x + off], s2 = ss[threadIdx.x + off];
                float m = fmaxf(m1, m2);
                ss[threadIdx.x]  = s1 * __expf(m1 - m) + s2 * __expf(m2 - m);
                smx[threadIdx.x] = m;
            }
            __syncthreads();
        }
        __shared__ float lp;
        if (threadIdx.x == 0) lp = smx[0] + __logf(ss[0]);
        __syncthreads();
        for (int m = threadIdx.x; m < NN; m += TPB)
            d_piadj[m] = pri[m] - lp - d_rowmax[m];
    }
}

// pre-gather emissions: emitg[t][b][m] = emission[m, x[b,t]] - rowlse[m] + rowmax[m]
__global__ void k_gather(const float* __restrict__ emis, const int* __restrict__ x) {
    int t = blockIdx.x % TT, b = blockIdx.x / TT;
    int tok = x[b * TT + t];
    float* dst = d_emitg + (size_t)(t * BB + b) * NN;
    for (int m = threadIdx.x; m < NN; m += TPB)
        dst[m] = __ldg(&emis[(size_t)m * VV + tok]) - d_rowlse[m] + d_rowmax[m];
}

// ---------------- persistent forward recursion ----------------
#define FWD_SMEM ((RR*NN + BB*NN + RR*BB) * 4)

__global__ void __launch_bounds__(TPB)
k_forward(const int* __restrict__ len, float* __restrict__ out) {
    extern __shared__ float sh[];
    float* E_sh     = sh;                 // [RR][NN]
    float* ea_sh    = sh + RR * NN;       // [BB][NN]
    float* alpha_sh = ea_sh + BB * NN;    // [RR][BB]
    __shared__ float gprev[BB], gcur[BB], easum_sh[BB];

    const int g = blockIdx.x, tid = threadIdx.x;
    const int w = tid >> 5, lane = tid & 31;
    const int mt = w >> 2, bt = w & 3;    // 2 m-tiles x 4 b-tiles (8 warps)

    // stage this CTA's E_T slice into smem (once)
    {
        const float4* src = (const float4*)(d_ET + (size_t)g * RR * NN);
        float4* dst = (float4*)E_sh;
        for (int i = tid; i < RR * NN / 4; i += TPB) dst[i] = src[i];
    }

    unsigned nbar = 0;

    for (int t = 0; t < TT; t++) {
        // -------- Phase A: alpha chunk for this CTA's RR rows --------
        if (t == 0) {
            if (tid < RR * BB) {
                int ml = tid / BB, b = tid % BB, m = g * RR + ml;
                alpha_sh[ml * BB + b] = d_emitg[(size_t)(b) * NN + m] + d_piadj[m];
            }
        } else {
            // prefetch emit terms (lane 0 holds the 4x4 tile results)
            float em[4][4];
            if (lane == 0) {
#pragma unroll
                for (int j = 0; j < 4; j++)
#pragma unroll
                    for (int k = 0; k < 4; k++) {
                        int m = g * RR + mt * 4 + j, b = bt * 4 + k;
                        em[j][k] = d_emitg[(size_t)(t * BB + b) * NN + m];
                    }
            }
            float acc[4][4];
#pragma unroll
            for (int j = 0; j < 4; j++)
#pragma unroll
                for (int k = 0; k < 4; k++) acc[j][k] = 0.f;

            const float* Eb = E_sh + mt * 4 * NN;
            const float* Ab = ea_sh + bt * 4 * NN;
#pragma unroll
            for (int i = 0; i < NN / 128; i++) {
                int n0 = (lane + i * 32) * 4;
                float4 e[4], a[4];
#pragma unroll
                for (int j = 0; j < 4; j++) e[j] = *(const float4*)(Eb + j * NN + n0);
#pragma unroll
                for (int k = 0; k < 4; k++) a[k] = *(const float4*)(Ab + k * NN + n0);
#pragma unroll
                for (int j = 0; j < 4; j++)
#pragma unroll
                    for (int k = 0; k < 4; k++) {
                        acc[j][k] += e[j].x * a[k].x;
                        acc[j][k] += e[j].y * a[k].y;
                        acc[j][k] += e[j].z * a[k].z;
                        acc[j][k] += e[j].w * a[k].w;
                    }
            }
            // lane reduce
#pragma unroll
            for (int j = 0; j < 4; j++)
#pragma unroll
                for (int k = 0; k < 4; k++)
#pragma unroll
                    for (int off = 16; off; off >>= 1)
                        acc[j][k] += __shfl_xor_sync(0xffffffffu, acc[j][k], off);

            if (lane == 0) {
#pragma unroll
                for (int j = 0; j < 4; j++)
#pragma unroll
                    for (int k = 0; k < 4; k++) {
                        int ml = mt * 4 + j, b = bt * 4 + k;
                        alpha_sh[ml * BB + b] =
                            em[j][k] + gprev[b] + __logf(acc[j][k]);
                    }
            }
        }
        __syncthreads();

        // local max per batch -> global keyed atomicMax
        if (tid < BB) {
            float mxv = alpha_sh[tid];
#pragma unroll
            for (int ml = 1; ml < RR; ml++)
                mxv = fmaxf(mxv, alpha_sh[ml * BB + tid]);
            atomicMax(&d_gmaxkey[t * BB + tid], fkey(mxv));
        }
        nbar++; gbar(nbar * GG);

        // -------- Phase B: ea chunk + per-batch partial sums --------
        if (tid < BB) { gcur[tid] = funkey(d_gmaxkey[t * BB + tid]); easum_sh[tid] = 0.f; }
        __syncthreads();
        if (tid < RR * BB) {
            int ml = tid / BB, b = tid % BB, m = g * RR + ml;
            float e = __expf(alpha_sh[ml * BB + b] - gcur[b]);
            d_eag[b * NN + m] = e;
            atomicAdd(&easum_sh[b], e);
        }
        __syncthreads();
        if (tid < BB) {
            atomicAdd(&d_easum[t * BB + tid], easum_sh[tid]);
            gprev[tid] = gcur[tid];
        }
        nbar++; gbar(nbar * GG);

        // -------- Phase C: reload full ea into smem (not needed on last t) ----
        if (t < TT - 1) {
            const float4* src = (const float4*)d_eag;
            float4* dst = (float4*)ea_sh;
            for (int i = tid; i < BB * NN / 4; i += TPB) dst[i] = src[i];
            __syncthreads();
        }
    }

    // final output: sums_log[b, length-1] = gmax + log(sum ea)
    if (g == 0 && tid < BB) {
        int tb = len[tid] - 1;
        tb = tb < 0 ? 0 : (tb > TT - 1 ? TT - 1 : tb);
        out[tid] = funkey(d_gmaxkey[tb * BB + tid]) + __logf(d_easum[tb * BB + tid]);
    }
}

// ---------------- launch ----------------
extern "C" void kernel_launch(void* const* d_in, const int* in_sizes, int n_in,
                              void* d_out, int out_size) {
    (void)in_sizes; (void)n_in; (void)out_size;
    const float* emis  = (const float*)d_in[0];  // (N, V)
    const float* trans = (const float*)d_in[1];  // (N, N)
    const float* pri   = (const float*)d_in[2];  // (N,)
    const int*   x     = (const int*)d_in[3];    // (B, T)
    const int*   len   = (const int*)d_in[4];    // (B,)
    float*       out   = (float*)d_out;          // (B, 1)

    cudaFuncSetAttribute(k_forward, cudaFuncAttributeMaxDynamicSharedMemorySize,
                         FWD_SMEM);

    k_rowlse<<<NN, TPB>>>(emis);
    k_collse<<<NN / 32, dim3(32, 8)>>>(trans);
    k_prepT<<<NN, TPB>>>(trans);
    k_init<<<16, TPB>>>(pri);
    k_gather<<<BB * TT, TPB>>>(emis, x);
    k_forward<<<GG, TPB, FWD_SMEM>>>(len, out);
}

// round 2
// speedup vs baseline: 1.4537x; 1.4537x over previous
#include <cuda_runtime.h>
#include <math_constants.h>

#define NN  1024
#define VV  32000
#define BB  16
#define TT  128
#define GG  128            // CTAs in forward kernel (all co-resident)
#define RR  (NN/GG)        // 8 rows of E_T per CTA
#define TPB 256

// ---------------- device scratch (static; no runtime alloc) ----------------
__device__ float    d_ET[NN*NN];        // exp(log_T - rowmax), 4 MB
__device__ float    d_rowmax[NN];
__device__ float    d_rowlse[NN];
__device__ float    d_collse[NN];
__device__ float    d_piadj[NN];        // log_pi - rowmax
__device__ float    d_emitg[TT*NN*BB];  // emit + rowmax, layout [t][m][b], 8 MB
__device__ float    d_eag[BB*NN];       // exp(alpha - shift), layout [b][n]
__device__ unsigned d_gmaxkey[TT*BB];   // keyed-float atomicMax history
__device__ float    d_easum[TT*BB];     // sum_n ea per (t,b)
__device__ float    d_shift[TT*BB];     // shift used per (t,b)
__device__ unsigned d_barcnt;           // grid barrier counter

// ---------------- helpers ----------------
__device__ __forceinline__ unsigned fkey(float f) {
    unsigned u = __float_as_uint(f);
    return (u & 0x80000000u) ? ~u : (u | 0x80000000u);
}
__device__ __forceinline__ float funkey(unsigned k) {
    return (k & 0x80000000u) ? __uint_as_float(k & 0x7fffffffu)
                             : __uint_as_float(~k);
}
__device__ __forceinline__ unsigned long long ffma2(
    unsigned long long a, unsigned long long b, unsigned long long c) {
    unsigned long long d;
    asm("fma.rn.f32x2 %0, %1, %2, %3;" : "=l"(d) : "l"(a), "l"(b), "l"(c));
    return d;
}
__device__ __forceinline__ void cp_async16(unsigned dst_smem, const void* src) {
    asm volatile("cp.async.cg.shared.global [%0], [%1], 16;"
                 :: "r"(dst_smem), "l"(src));
}

// grid barrier: all-thread release fence, tid0 signals + tight spin
__device__ __forceinline__ void gbar(unsigned target) {
    __threadfence();
    __syncthreads();
    if (threadIdx.x == 0) {
        atomicAdd(&d_barcnt, 1u);
        while (*((volatile unsigned*)&d_barcnt) < target) { }
        __threadfence();                 // IVALL: L1 fresh for post-barrier loads
    }
    __syncthreads();
}

// ---------------- prep kernels ----------------
__global__ void k_rowlse(const float* __restrict__ emis) {
    int n = blockIdx.x;
    const float* row = emis + (size_t)n * VV;
    float mx = -CUDART_INF_F, s = 0.f;
    for (int i = threadIdx.x; i < VV; i += TPB) {
        float v = row[i];
        if (v > mx) { s = s * __expf(mx - v) + 1.f; mx = v; }
        else        { s += __expf(v - mx); }
    }
    __shared__ float smx[TPB], ss[TPB];
    smx[threadIdx.x] = mx; ss[threadIdx.x] = s;
    __syncthreads();
    for (int off = TPB / 2; off; off >>= 1) {
        if (threadIdx.x < off) {
            float m1 = smx[threadIdx.x], s1 = ss[threadIdx.x];
            float m2 = smx[threadIdx.x + off], s2 = ss[threadIdx.x + off];
            float m = fmaxf(m1, m2);
            ss[threadIdx.x]  = s1 * __expf(m1 - m) + s2 * __expf(m2 - m);
            smx[threadIdx.x] = m;
        }
        __syncthreads();
    }
    if (threadIdx.x == 0) d_rowlse[n] = smx[0] + __logf(ss[0]);
}

__global__ void k_collse(const float* __restrict__ trans) {
    int col = blockIdx.x * 32 + threadIdx.x;   // threadIdx.x in [0,32)
    int ty  = threadIdx.y;                     // [0,8)
    float mx = -CUDART_INF_F, s = 0.f;
    for (int m = ty; m < NN; m += 8) {
        float v = trans[m * NN + col];
        if (v > mx) { s = s * __expf(mx - v) + 1.f; mx = v; }
        else        { s += __expf(v - mx); }
    }
    __shared__ float smx[8][32], ss[8][32];
    smx[ty][threadIdx.x] = mx; ss[ty][threadIdx.x] = s;
    __syncthreads();
    if (ty == 0) {
        float m1 = mx, s1 = s;
        for (int j = 1; j < 8; j++) {
            float m2 = smx[j][threadIdx.x], s2 = ss[j][threadIdx.x];
            float m = fmaxf(m1, m2);
            s1 = s1 * __expf(m1 - m) + s2 * __expf(m2 - m);
            m1 = m;
        }
        d_collse[col] = m1 + __logf(s1);
    }
}

__global__ void k_prepT(const float* __restrict__ trans) {
    int m = blockIdx.x;
    const float* rowp = trans + (size_t)m * NN;
    float mx = -CUDART_INF_F;
    for (int n = threadIdx.x; n < NN; n += TPB)
        mx = fmaxf(mx, rowp[n] - d_collse[n]);
    __shared__ float smx[TPB];
    smx[threadIdx.x] = mx; __syncthreads();
    for (int off = TPB / 2; off; off >>= 1) {
        if (threadIdx.x < off)
            smx[threadIdx.x] = fmaxf(smx[threadIdx.x], smx[threadIdx.x + off]);
        __syncthreads();
    }
    float rm = smx[0];
    if (threadIdx.x == 0) d_rowmax[m] = rm;
    for (int n = threadIdx.x; n < NN; n += TPB)
        d_ET[m * NN + n] = __expf(rowp[n] - d_collse[n] - rm);
}

__global__ void k_init(const float* __restrict__ pri) {
    int base = blockIdx.x * 128;
    if (threadIdx.x < 128) {
        d_gmaxkey[base + threadIdx.x] = 0u;
        d_easum[base + threadIdx.x]   = 0.f;
    }
    if (blockIdx.x == 0) {
        if (threadIdx.x == 0) d_barcnt = 0u;
        float mx = -CUDART_INF_F, s = 0.f;
        for (int i = threadIdx.x; i < NN; i += TPB) {
            float v = pri[i];
            if (v > mx) { s = s * __expf(mx - v) + 1.f; mx = v; }
            else        { s += __expf(v - mx); }
        }
        __shared__ float smx[TPB], ss[TPB];
        smx[threadIdx.x] = mx; ss[threadIdx.x] = s;
        __syncthreads();
        for (int off = TPB / 2; off; off >>= 1) {
            if (threadIdx.x < off) {
                float m1 = smx[threadIdx.x], s1 = ss[threadIdx.x];
                float m2 = smx[threadIdx.x + off], s2 = ss[threadIdx.x + off];
                float m = fmaxf(m1, m2);
                ss[threadIdx.x]  = s1 * __expf(m1 - m) + s2 * __expf(m2 - m);
                smx[threadIdx.x] = m;
            }
            __syncthreads();
        }
        __shared__ float lp;
        if (threadIdx.x == 0) lp = smx[0] + __logf(ss[0]);
        __syncthreads();
        for (int m = threadIdx.x; m < NN; m += TPB)
            d_piadj[m] = pri[m] - lp - d_rowmax[m];
    }
}

// emitg[t][m][b] = emission[m, x[b,t]] - rowlse[m] + rowmax[m]; coalesced writes
__global__ void k_gather(const float* __restrict__ emis, const int* __restrict__ x) {
    int t = blockIdx.x;
    __shared__ int tok[BB];
    if (threadIdx.x < BB) tok[threadIdx.x] = x[threadIdx.x * TT + t];
    __syncthreads();
    float* dst = d_emitg + (size_t)t * NN * BB;
    for (int i = threadIdx.x; i < NN * BB; i += TPB) {
        int m = i >> 4, b = i & 15;
        dst[i] = __ldg(&emis[(size_t)m * VV + tok[b]]) - d_rowlse[m] + d_rowmax[m];
    }
}

// ---------------- persistent forward recursion ----------------
#define FWD_SMEM ((RR*NN + BB*NN + 2*RR*BB) * 4)

__global__ void __launch_bounds__(TPB, 1)
k_forward(const int* __restrict__ len, float* __restrict__ out) {
    extern __shared__ float sh[];
    float* E_sh     = sh;                     // [RR][NN]
    float* ea_sh    = sh + RR * NN;           // [BB][NN]
    float* alpha_sh = ea_sh + BB * NN;        // [RR*BB]
    float* eat_sh   = alpha_sh + RR * BB;     // [RR*BB]
    __shared__ float sA[BB], sB[BB];          // shift(t-1), shift(t)

    const int g = blockIdx.x, tid = threadIdx.x;
    const int w = tid >> 5, lane = tid & 31;
    // matvec warps 0..3: tile 4m x 8b, full n
    const int mt = w & 1, bt = (w >> 1) & 1;
    const bool mat = (w < 4);
    const unsigned ea_smem =
        (unsigned)__cvta_generic_to_shared(ea_sh);

    // stage E_T slice
    {
        const float4* src = (const float4*)(d_ET + (size_t)g * RR * NN);
        float4* dst = (float4*)E_sh;
        for (int i = tid; i < RR * NN / 4; i += TPB) dst[i] = src[i];
    }
    if (tid < BB) { sA[tid] = 0.f; sB[tid] = 0.f; }
    float g1 = 0.f;                            // gmax[t-1] (tid<16 threads)
    __syncthreads();

    const float* Eb = E_sh + (mt * 4) * NN;
    const float* Ab = ea_sh + (bt * 8) * NN;

    for (int t = 0; t < TT; t++) {
        // -------- matvec over 4 n-chunks (pipelined with cp.async reload) ----
        unsigned long long acc[4][8];
        if (t > 0 && mat) {
#pragma unroll
            for (int j = 0; j < 4; j++)
#pragma unroll
                for (int k = 0; k < 8; k++) acc[j][k] = 0ull;
        }
#pragma unroll
        for (int c = 0; c < 4; c++) {
            if (t > 0) {
                if      (c == 0) asm volatile("cp.async.wait_group 3;");
                else if (c == 1) asm volatile("cp.async.wait_group 2;");
                else if (c == 2) asm volatile("cp.async.wait_group 1;");
                else             asm volatile("cp.async.wait_group 0;");
            }
            __syncthreads();
            if (t > 0 && mat) {
#pragma unroll
                for (int i2 = 0; i2 < 2; i2++) {
                    int n0 = c * 256 + (i2 * 32 + lane) * 4;
                    ulonglong2 e[4], a[8];
#pragma unroll
                    for (int j = 0; j < 4; j++)
                        e[j] = *(const ulonglong2*)(Eb + j * NN + n0);
#pragma unroll
                    for (int k = 0; k < 8; k++)
                        a[k] = *(const ulonglong2*)(Ab + k * NN + n0);
#pragma unroll
                    for (int j = 0; j < 4; j++)
#pragma unroll
                        for (int k = 0; k < 8; k++) {
                            acc[j][k] = ffma2(e[j].x, a[k].x, acc[j][k]);
                            acc[j][k] = ffma2(e[j].y, a[k].y, acc[j][k]);
                        }
                }
            }
        }
        if (t > 0 && mat) {
            // fold f32x2 + lane reduce
            float r[4][8];
#pragma unroll
            for (int j = 0; j < 4; j++)
#pragma unroll
                for (int k = 0; k < 8; k++) {
                    float2 f = *(float2*)&acc[j][k];
                    r[j][k] = f.x + f.y;
                }
#pragma unroll
            for (int off = 16; off; off >>= 1)
#pragma unroll
                for (int j = 0; j < 4; j++)
#pragma unroll
                    for (int k = 0; k < 8; k++)
                        r[j][k] += __shfl_xor_sync(0xffffffffu, r[j][k], off);
            if (lane == 0) {
#pragma unroll
                for (int j = 0; j < 4; j++)
#pragma unroll
                    for (int k = 0; k < 8; k++)
                        alpha_sh[(mt * 4 + j) * BB + bt * 8 + k] = r[j][k];
            }
        }
        __syncthreads();

        // -------- finalize: alpha, ea, local stats --------
        if (tid < RR * BB) {
            int ml = tid >> 4, b = tid & 15, m = g * RR + ml;
            float A;
            if (t == 0)
                A = d_emitg[(size_t)m * BB + b] + d_piadj[m];
            else
                A = d_emitg[((size_t)t * NN + m) * BB + b] + sA[b] +
                    __logf(alpha_sh[tid]);
            float e = __expf(A - sB[b]);
            d_eag[b * NN + m] = e;
            alpha_sh[tid] = A;
            eat_sh[tid]   = e;
        }
        __syncthreads();
        if (tid < BB) {
            float mxv = alpha_sh[tid], sm = eat_sh[tid];
#pragma unroll
            for (int ml = 1; ml < RR; ml++) {
                mxv = fmaxf(mxv, alpha_sh[ml * BB + tid]);
                sm += eat_sh[ml * BB + tid];
            }
            atomicMax(&d_gmaxkey[t * BB + tid], fkey(mxv));
            atomicAdd(&d_easum[t * BB + tid], sm);
            if (g == 0) d_shift[t * BB + tid] = sB[tid];
        }

        gbar((unsigned)(t + 1) * GG);

        // -------- shift predictor for t+1 --------
        if (tid < BB) {
            float g0 = funkey(d_gmaxkey[t * BB + tid]);
            float d  = fminf(10.f, fmaxf(-30.f, g0 - g1));
            sA[tid] = sB[tid];
            sB[tid] = g0 + d;
            g1 = g0;
        }
        // no syncthreads needed: sA/sB consumed after chunk syncthreads below

        // -------- issue async reload of ea for t+1 --------
        if (t < TT - 1) {
#pragma unroll
            for (int c = 0; c < 4; c++) {
#pragma unroll
                for (int k = 0; k < 4; k++) {
                    int j4 = tid + 256 * k;          // [0,1024) float4 units
                    int b = j4 >> 6, nq = j4 & 63;
                    unsigned off = (unsigned)(b * 4096 + c * 1024 + nq * 16);
                    cp_async16(ea_smem + off, (const char*)d_eag + off);
                }
                asm volatile("cp.async.commit_group;");
            }
        }
    }

    // final output: out[b] = shift[len-1] + log(easum[len-1])
    if (g == 0 && tid < BB) {
        int tb = len[tid] - 1;
        tb = tb < 0 ? 0 : (tb > TT - 1 ? TT - 1 : tb);
        out[tid] = d_shift[tb * BB + tid] + __logf(d_easum[tb * BB + tid]);
    }
}

// ---------------- launch ----------------
extern "C" void kernel_launch(void* const* d_in, const int* in_sizes, int n_in,
                              void* d_out, int out_size) {
    (void)in_sizes; (void)n_in; (void)out_size;
    const float* emis  = (const float*)d_in[0];  // (N, V)
    const float* trans = (const float*)d_in[1];  // (N, N)
    const float* pri   = (const float*)d_in[2];  // (N,)
    const int*   x     = (const int*)d_in[3];    // (B, T)
    const int*   len   = (const int*)d_in[4];    // (B,)
    float*       out   = (float*)d_out;          // (B, 1)

    cudaFuncSetAttribute(k_forward, cudaFuncAttributeMaxDynamicSharedMemorySize,
                         FWD_SMEM);

    k_rowlse<<<NN, TPB>>>(emis);
    k_collse<<<NN / 32, dim3(32, 8)>>>(trans);
    k_prepT<<<NN, TPB>>>(trans);
    k_init<<<16, TPB>>>(pri);
    k_gather<<<TT, TPB>>>(emis, x);
    k_forward<<<GG, TPB, FWD_SMEM>>>(len, out);
}

// round 3
// speedup vs baseline: 1.7886x; 1.2304x over previous
#include <cuda_runtime.h>
#include <math_constants.h>

#define NN  1024
#define VV  32000
#define BB  16
#define TT  128
#define GG  128            // CTAs in forward kernel (all co-resident)
#define RR  (NN/GG)        // 8 rows of E_T per CTA
#define TPB 256

// ---------------- device scratch (static; no runtime alloc) ----------------
__device__ float          d_ET[NN*NN];        // exp(log_T' - rowmax), 4 MB
__device__ float          d_rowmax[NN];
__device__ float          d_rowlse[NN];
__device__ float          d_collse[NN];
__device__ float          d_piadj[NN];        // log_pi - rowmax
__device__ float          d_emitg[TT*NN*BB];  // emit - rowlse + rowmax, [t][m][b]
__device__ unsigned short d_eag[2][BB*NN];    // bf16 exp(alpha - shift), ping-pong
__device__ float          d_easum[TT*BB];     // sum_n ea per (t,b)
__device__ float          d_shift[TT*BB];     // shift used per (t,b)
__device__ unsigned       d_barcnt;           // grid barrier counter

// ---------------- helpers ----------------
__device__ __forceinline__ unsigned long long ffma2(
    unsigned long long a, unsigned long long b, unsigned long long c) {
    unsigned long long d;
    asm("fma.rn.f32x2 %0, %1, %2, %3;" : "=l"(d) : "l"(a), "l"(b), "l"(c));
    return d;
}
// bf16 pair (packed in u32) -> f32x2 (64-bit reg pair); bf16->f32 is a shift
__device__ __forceinline__ unsigned long long bf2f32x2(unsigned u) {
    unsigned lo = u << 16, hi = u & 0xffff0000u;
    unsigned long long p;
    asm("mov.b64 %0, {%1,%2};" : "=l"(p) : "r"(lo), "r"(hi));
    return p;
}
__device__ __forceinline__ void cp_async16(unsigned dst_smem, const void* src) {
    asm volatile("cp.async.cg.shared.global [%0], [%1], 16;"
                 :: "r"(dst_smem), "l"(src));
}
__device__ __forceinline__ unsigned bf16x2pack(float lo, float hi) {
    unsigned r;
    asm("cvt.rn.bf16x2.f32 %0, %1, %2;" : "=r"(r) : "f"(hi), "f"(lo));
    return r;
}

// lightweight grid barrier: release-arrive + acquire-spin (no full membars)
__device__ __forceinline__ void gbar(unsigned target) {
    __syncthreads();
    if (threadIdx.x == 0) {
        asm volatile("red.release.gpu.add.u32 [%0], 1;" :: "l"(&d_barcnt));
        unsigned v;
        do {
            asm volatile("ld.acquire.gpu.u32 %0, [%1];" : "=r"(v) : "l"(&d_barcnt));
        } while (v < target);
    }
    __syncthreads();
}

// ---------------- prep kernels ----------------
__global__ void k_rowlse(const float* __restrict__ emis) {
    int n = blockIdx.x;
    const float* row = emis + (size_t)n * VV;
    float mx = -CUDART_INF_F, s = 0.f;
    for (int i = threadIdx.x; i < VV; i += TPB) {
        float v = row[i];
        if (v > mx) { s = s * __expf(mx - v) + 1.f; mx = v; }
        else        { s += __expf(v - mx); }
    }
    __shared__ float smx[TPB], ss[TPB];
    smx[threadIdx.x] = mx; ss[threadIdx.x] = s;
    __syncthreads();
    for (int off = TPB / 2; off; off >>= 1) {
        if (threadIdx.x < off) {
            float m1 = smx[threadIdx.x], s1 = ss[threadIdx.x];
            float m2 = smx[threadIdx.x + off], s2 = ss[threadIdx.x + off];
            float m = fmaxf(m1, m2);
            ss[threadIdx.x]  = s1 * __expf(m1 - m) + s2 * __expf(m2 - m);
            smx[threadIdx.x] = m;
        }
        __syncthreads();
    }
    if (threadIdx.x == 0) d_rowlse[n] = smx[0] + __logf(ss[0]);
}

__global__ void k_collse(const float* __restrict__ trans) {
    int col = blockIdx.x * 32 + threadIdx.x;
    int ty  = threadIdx.y;
    float mx = -CUDART_INF_F, s = 0.f;
    for (int m = ty; m < NN; m += 8) {
        float v = trans[m * NN + col];
        if (v > mx) { s = s * __expf(mx - v) + 1.f; mx = v; }
        else        { s += __expf(v - mx); }
    }
    __shared__ float smx[8][32], ss[8][32];
    smx[ty][threadIdx.x] = mx; ss[ty][threadIdx.x] = s;
    __syncthreads();
    if (ty == 0) {
        float m1 = mx, s1 = s;
        for (int j = 1; j < 8; j++) {
            float m2 = smx[j][threadIdx.x], s2 = ss[j][threadIdx.x];
            float m = fmaxf(m1, m2);
            s1 = s1 * __expf(m1 - m) + s2 * __expf(m2 - m);
            m1 = m;
        }
        d_collse[col] = m1 + __logf(s1);
    }
}

__global__ void k_prepT(const float* __restrict__ trans) {
    int m = blockIdx.x;
    const float* rowp = trans + (size_t)m * NN;
    float mx = -CUDART_INF_F;
    for (int n = threadIdx.x; n < NN; n += TPB)
        mx = fmaxf(mx, rowp[n] - d_collse[n]);
    __shared__ float smx[TPB];
    smx[threadIdx.x] = mx; __syncthreads();
    for (int off = TPB / 2; off; off >>= 1) {
        if (threadIdx.x < off)
            smx[threadIdx.x] = fmaxf(smx[threadIdx.x], smx[threadIdx.x + off]);
        __syncthreads();
    }
    float rm = smx[0];
    if (threadIdx.x == 0) d_rowmax[m] = rm;
    for (int n = threadIdx.x; n < NN; n += TPB)
        d_ET[m * NN + n] = __expf(rowp[n] - d_collse[n] - rm);
}

__global__ void k_init(const float* __restrict__ pri) {
    int base = blockIdx.x * 128;
    if (threadIdx.x < 128) d_easum[base + threadIdx.x] = 0.f;
    if (blockIdx.x == 0) {
        if (threadIdx.x == 0) d_barcnt = 0u;
        float mx = -CUDART_INF_F, s = 0.f;
        for (int i = threadIdx.x; i < NN; i += TPB) {
            float v = pri[i];
            if (v > mx) { s = s * __expf(mx - v) + 1.f; mx = v; }
            else        { s += __expf(v - mx); }
        }
        __shared__ float smx[TPB], ss[TPB];
        smx[threadIdx.x] = mx; ss[threadIdx.x] = s;
        __syncthreads();
        for (int off = TPB / 2; off; off >>= 1) {
            if (threadIdx.x < off) {
                float m1 = smx[threadIdx.x], s1 = ss[threadIdx.x];
                float m2 = smx[threadIdx.x + off], s2 = ss[threadIdx.x + off];
                float m = fmaxf(m1, m2);
                ss[threadIdx.x]  = s1 * __expf(m1 - m) + s2 * __expf(m2 - m);
                smx[threadIdx.x] = m;
            }
            __syncthreads();
        }
        __shared__ float lp;
        if (threadIdx.x == 0) lp = smx[0] + __logf(ss[0]);
        __syncthreads();
        for (int m = threadIdx.x; m < NN; m += TPB)
            d_piadj[m] = pri[m] - lp - d_rowmax[m];
    }
}

__global__ void k_gather(const float* __restrict__ emis, const int* __restrict__ x) {
    int t = blockIdx.x;
    __shared__ int tok[BB];
    if (threadIdx.x < BB) tok[threadIdx.x] = x[threadIdx.x * TT + t];
    __syncthreads();
    float* dst = d_emitg + (size_t)t * NN * BB;
    for (int i = threadIdx.x; i < NN * BB; i += TPB) {
        int m = i >> 4, b = i & 15;
        dst[i] = __ldg(&emis[(size_t)m * VV + tok[b]]) - d_rowlse[m] + d_rowmax[m];
    }
}

// ---------------- persistent forward recursion ----------------
// smem: E (fp32, 32KB) + ea (bf16, 32KB) + alpha partials + ea temp
#define FWD_SMEM (RR*NN*4 + BB*NN*2 + 2*RR*BB*4)

__global__ void __launch_bounds__(TPB, 1)
k_forward(const int* __restrict__ len, float* __restrict__ out) {
    extern __shared__ float sh[];
    float* E_sh     = sh;                               // [RR][NN] fp32
    char*  ea_sh    = (char*)(sh + RR * NN);            // [BB][NN] bf16 (2KB/row)
    float* alpha_sh = (float*)(ea_sh + BB * NN * 2);    // [RR*BB] matvec partials
    float* eat_sh   = alpha_sh + RR * BB;               // [RR*BB] ea temp
    __shared__ float sA[BB], sB[BB];                    // shift(t-1), shift(t)

    const int g = blockIdx.x, tid = threadIdx.x;
    const int w = tid >> 5, lane = tid & 31;
    const int mt = w & 1, bt = (w >> 1) & 1;            // warps 0..3: 4m x 8b, full n
    const bool mat = (w < 4);
    const unsigned ea_smem = (unsigned)__cvta_generic_to_shared(ea_sh);

    // stage E_T slice once
    {
        const float4* src = (const float4*)(d_ET + (size_t)g * RR * NN);
        float4* dst = (float4*)E_sh;
        for (int i = tid; i < RR * NN / 4; i += TPB) dst[i] = src[i];
    }
    if (tid < BB) { sA[tid] = 0.f; sB[tid] = 0.f; }
    float lseP = 0.f;                                   // lse(t-1), tid<16 only
    __syncthreads();

    const float* Eb  = E_sh + (mt * 4) * NN;
    const char*  AbB = ea_sh + (bt * 8) * (NN * 2);

    const int ml_f = tid >> 4, b_f = tid & 15, m_f = g * RR + ml_f;  // finalize ids

    for (int t = 0; t < TT; t++) {
        // emit prefetch (L2 latency hides under matvec)
        float em = 0.f, pa = 0.f;
        if (tid < RR * BB) {
            em = __ldcg(&d_emitg[((size_t)t * NN + m_f) * BB + b_f]);
            if (t == 0) pa = __ldcg(&d_piadj[m_f]);
        }

        // -------- matvec over 4 n-chunks (pipelined with cp.async reload) ----
        if (t > 0) {
            unsigned long long acc[4][8];
            if (mat) {
#pragma unroll
                for (int j = 0; j < 4; j++)
#pragma unroll
                    for (int k = 0; k < 8; k++) acc[j][k] = 0ull;
            }
#pragma unroll
            for (int c = 0; c < 4; c++) {
                if      (c == 0) asm volatile("cp.async.wait_group 3;");
                else if (c == 1) asm volatile("cp.async.wait_group 2;");
                else if (c == 2) asm volatile("cp.async.wait_group 1;");
                else             asm volatile("cp.async.wait_group 0;");
                __syncthreads();
                if (mat) {
#pragma unroll
                    for (int i2 = 0; i2 < 2; i2++) {
                        int n0 = c * 256 + (i2 * 32 + lane) * 4;
                        ulonglong2 e[4];
#pragma unroll
                        for (int j = 0; j < 4; j++)
                            e[j] = *(const ulonglong2*)(Eb + j * NN + n0);
#pragma unroll
                        for (int k = 0; k < 8; k++) {
                            uint2 av = *(const uint2*)(AbB + k * (NN * 2) + n0 * 2);
                            unsigned long long a0 = bf2f32x2(av.x);
                            unsigned long long a1 = bf2f32x2(av.y);
#pragma unroll
                            for (int j = 0; j < 4; j++) {
                                acc[j][k] = ffma2(e[j].x, a0, acc[j][k]);
                                acc[j][k] = ffma2(e[j].y, a1, acc[j][k]);
                            }
                        }
                    }
                }
            }
            if (mat) {
                float r[4][8];
#pragma unroll
                for (int j = 0; j < 4; j++)
#pragma unroll
                    for (int k = 0; k < 8; k++) {
                        float2 f = *(float2*)&acc[j][k];
                        r[j][k] = f.x + f.y;
                    }
#pragma unroll
                for (int off = 16; off; off >>= 1)
#pragma unroll
                    for (int j = 0; j < 4; j++)
#pragma unroll
                        for (int k = 0; k < 8; k++)
                            r[j][k] += __shfl_xor_sync(0xffffffffu, r[j][k], off);
                if (lane == 0) {
#pragma unroll
                    for (int j = 0; j < 4; j++)
#pragma unroll
                        for (int k = 0; k < 8; k++)
                            alpha_sh[(mt * 4 + j) * BB + bt * 8 + k] = r[j][k];
                }
            }
            __syncthreads();
        }

        // -------- finalize: alpha -> ea (shifted), store temp --------
        if (tid < RR * BB) {
            float A = (t == 0) ? (em + pa)
                               : (em + sA[b_f] + __logf(alpha_sh[tid]));
            eat_sh[tid] = __expf(A - sB[b_f]);
        }
        __syncthreads();

        // pack bf16 pairs -> d_eag[t&1]  (64 threads, 1 STG.32 each)
        if (tid < 64) {
            int b = tid >> 2, q = tid & 3;
            float e0 = eat_sh[(2 * q) * BB + b];
            float e1 = eat_sh[(2 * q + 1) * BB + b];
            unsigned* dst = (unsigned*)&d_eag[t & 1][b * NN + g * RR + 2 * q];
            *dst = bf16x2pack(e0, e1);
        }
        // per-batch partial sums -> global (REDG, no return)
        if (tid < BB) {
            float sm = eat_sh[tid];
#pragma unroll
            for (int ml = 1; ml < RR; ml++) sm += eat_sh[ml * BB + tid];
            atomicAdd(&d_easum[t * BB + tid], sm);
            if (g == 0) d_shift[t * BB + tid] = sB[tid];
        }

        gbar((unsigned)(t + 1) * GG);

        // -------- shift predictor from exact running lse --------
        if (tid < BB) {
            float sum = __ldcg(&d_easum[t * BB + tid]);
            float lse = sB[tid] + __logf(sum);
            float d   = (t == 0) ? 0.f
                                 : fminf(20.f, fmaxf(-40.f, lse - lseP));
            sA[tid] = sB[tid];
            sB[tid] = lse + d;
            lseP = lse;
        }

        // -------- issue async reload of ea(t) for step t+1 --------
        if (t < TT - 1) {
            const char* src_base = (const char*)d_eag[t & 1];
#pragma unroll
            for (int c = 0; c < 4; c++) {
#pragma unroll
                for (int k = 0; k < 2; k++) {
                    int idx = tid + 256 * k;             // [0,512) 16B units
                    int b = idx >> 5, o = idx & 31;
                    unsigned off = (unsigned)(b * (NN * 2) + c * 512 + o * 16);
                    cp_async16(ea_smem + off, src_base + off);
                }
                asm volatile("cp.async.commit_group;");
            }
        }
    }

    // final output: out[b] = shift[len-1] + log(easum[len-1])
    if (g == 0 && tid < BB) {
        int tb = len[tid] - 1;
        tb = tb < 0 ? 0 : (tb > TT - 1 ? TT - 1 : tb);
        out[tid] = d_shift[tb * BB + tid] + __logf(__ldcg(&d_easum[tb * BB + tid]));
    }
}

// ---------------- launch ----------------
extern "C" void kernel_launch(void* const* d_in, const int* in_sizes, int n_in,
                              void* d_out, int out_size) {
    (void)in_sizes; (void)n_in; (void)out_size;
    const float* emis  = (const float*)d_in[0];  // (N, V)
    const float* trans = (const float*)d_in[1];  // (N, N)
    const float* pri   = (const float*)d_in[2];  // (N,)
    const int*   x     = (const int*)d_in[3];    // (B, T)
    const int*   len   = (const int*)d_in[4];    // (B,)
    float*       out   = (float*)d_out;          // (B, 1)

    cudaFuncSetAttribute(k_forward, cudaFuncAttributeMaxDynamicSharedMemorySize,
                         FWD_SMEM);

    k_rowlse<<<NN, TPB>>>(emis);
    k_collse<<<NN / 32, dim3(32, 8)>>>(trans);
    k_prepT<<<NN, TPB>>>(trans);
    k_init<<<16, TPB>>>(pri);
    k_gather<<<TT, TPB>>>(emis, x);
    k_forward<<<GG, TPB, FWD_SMEM>>>(len, out);
}

// round 4
// speedup vs baseline: 1.8612x; 1.0405x over previous
#include <cuda_runtime.h>
#include <math_constants.h>

#define NN  1024
#define VV  32000
#define BB  16
#define TT  128
#define GG  128            // CTAs in forward kernel (all co-resident)
#define RR  (NN/GG)        // 8 rows of E_T per CTA
#define TPB 256

// ---------------- device scratch (static; no runtime alloc) ----------------
__device__ unsigned short d_ETh[NN*NN];       // bf16 exp(log_T' - rowmax), 2 MB
__device__ float          d_rowmax[NN];
__device__ float          d_rowlse[NN];
__device__ float          d_collse[NN];
__device__ float          d_piadj[NN];        // log_pi - rowmax
__device__ float          d_emitg[TT*NN*BB];  // emit - rowlse + rowmax, [t][m][b]
__device__ unsigned short d_eag[2][BB*NN];    // bf16 exp(alpha - shift), ping-pong
__device__ float          d_easum[TT*BB];     // sum_n ea per (t,b)
__device__ float          d_shift[TT*BB];     // shift used per (t,b)
__device__ unsigned       d_barcnt;           // grid barrier counter

// ---------------- helpers ----------------
__device__ __forceinline__ unsigned long long ffma2(
    unsigned long long a, unsigned long long b, unsigned long long c) {
    unsigned long long d;
    asm("fma.rn.f32x2 %0, %1, %2, %3;" : "=l"(d) : "l"(a), "l"(b), "l"(c));
    return d;
}
// bf16 pair (packed u32, lo = element 0) -> f32x2 (64-bit reg pair)
__device__ __forceinline__ unsigned long long bf2f32x2(unsigned u) {
    unsigned lo = u << 16, hi = u & 0xffff0000u;
    unsigned long long p;
    asm("mov.b64 %0, {%1,%2};" : "=l"(p) : "r"(lo), "r"(hi));
    return p;
}
__device__ __forceinline__ void cp_async16(unsigned dst_smem, const void* src) {
    asm volatile("cp.async.cg.shared.global [%0], [%1], 16;"
                 :: "r"(dst_smem), "l"(src));
}
__device__ __forceinline__ unsigned bf16x2pack(float lo, float hi) {
    unsigned r;
    asm("cvt.rn.bf16x2.f32 %0, %1, %2;" : "=r"(r) : "f"(hi), "f"(lo));
    return r;
}

// lightweight grid barrier: release-arrive + acquire-spin (no full membars)
__device__ __forceinline__ void gbar(unsigned target) {
    __syncthreads();
    if (threadIdx.x == 0) {
        asm volatile("red.release.gpu.add.u32 [%0], 1;" :: "l"(&d_barcnt));
        unsigned v;
        do {
            asm volatile("ld.acquire.gpu.u32 %0, [%1];" : "=r"(v) : "l"(&d_barcnt));
        } while (v < target);
    }
    __syncthreads();
}

// ---------------- prep kernels ----------------
__global__ void k_rowlse(const float* __restrict__ emis) {
    int n = blockIdx.x;
    const float* row = emis + (size_t)n * VV;
    float mx = -CUDART_INF_F, s = 0.f;
    for (int i = threadIdx.x; i < VV; i += TPB) {
        float v = row[i];
        if (v > mx) { s = s * __expf(mx - v) + 1.f; mx = v; }
        else        { s += __expf(v - mx); }
    }
    __shared__ float smx[TPB], ss[TPB];
    smx[threadIdx.x] = mx; ss[threadIdx.x] = s;
    __syncthreads();
    for (int off = TPB / 2; off; off >>= 1) {
        if (threadIdx.x < off) {
            float m1 = smx[threadIdx.x], s1 = ss[threadIdx.x];
            float m2 = smx[threadIdx.x + off], s2 = ss[threadIdx.x + off];
            float m = fmaxf(m1, m2);
            ss[threadIdx.x]  = s1 * __expf(m1 - m) + s2 * __expf(m2 - m);
            smx[threadIdx.x] = m;
        }
        __syncthreads();
    }
    if (threadIdx.x == 0) d_rowlse[n] = smx[0] + __logf(ss[0]);
}

__global__ void k_collse(const float* __restrict__ trans) {
    int col = blockIdx.x * 32 + threadIdx.x;
    int ty  = threadIdx.y;
    float mx = -CUDART_INF_F, s = 0.f;
    for (int m = ty; m < NN; m += 8) {
        float v = trans[m * NN + col];
        if (v > mx) { s = s * __expf(mx - v) + 1.f; mx = v; }
        else        { s += __expf(v - mx); }
    }
    __shared__ float smx[8][32], ss[8][32];
    smx[ty][threadIdx.x] = mx; ss[ty][threadIdx.x] = s;
    __syncthreads();
    if (ty == 0) {
        float m1 = mx, s1 = s;
        for (int j = 1; j < 8; j++) {
            float m2 = smx[j][threadIdx.x], s2 = ss[j][threadIdx.x];
            float m = fmaxf(m1, m2);
            s1 = s1 * __expf(m1 - m) + s2 * __expf(m2 - m);
            m1 = m;
        }
        d_collse[col] = m1 + __logf(s1);
    }
}

__global__ void k_prepT(const float* __restrict__ trans) {
    int m = blockIdx.x;
    const float* rowp = trans + (size_t)m * NN;
    float mx = -CUDART_INF_F;
    for (int n = threadIdx.x; n < NN; n += TPB)
        mx = fmaxf(mx, rowp[n] - d_collse[n]);
    __shared__ float smx[TPB];
    smx[threadIdx.x] = mx; __syncthreads();
    for (int off = TPB / 2; off; off >>= 1) {
        if (threadIdx.x < off)
            smx[threadIdx.x] = fmaxf(smx[threadIdx.x], smx[threadIdx.x + off]);
        __syncthreads();
    }
    float rm = smx[0];
    if (threadIdx.x == 0) d_rowmax[m] = rm;
    for (int n = threadIdx.x; n < NN; n += TPB) {
        float e = __expf(rowp[n] - d_collse[n] - rm);
        unsigned r;
        asm("cvt.rn.bf16x2.f32 %0, %1, %2;" : "=r"(r) : "f"(0.f), "f"(e));
        d_ETh[m * NN + n] = (unsigned short)(r & 0xffffu);
    }
}

__global__ void k_init(const float* __restrict__ pri) {
    int base = blockIdx.x * 128;
    if (threadIdx.x < 128) d_easum[base + threadIdx.x] = 0.f;
    if (blockIdx.x == 0) {
        if (threadIdx.x == 0) d_barcnt = 0u;
        float mx = -CUDART_INF_F, s = 0.f;
        for (int i = threadIdx.x; i < NN; i += TPB) {
            float v = pri[i];
            if (v > mx) { s = s * __expf(mx - v) + 1.f; mx = v; }
            else        { s += __expf(v - mx); }
        }
        __shared__ float smx[TPB], ss[TPB];
        smx[threadIdx.x] = mx; ss[threadIdx.x] = s;
        __syncthreads();
        for (int off = TPB / 2; off; off >>= 1) {
            if (threadIdx.x < off) {
                float m1 = smx[threadIdx.x], s1 = ss[threadIdx.x];
                float m2 = smx[threadIdx.x + off], s2 = ss[threadIdx.x + off];
                float m = fmaxf(m1, m2);
                ss[threadIdx.x]  = s1 * __expf(m1 - m) + s2 * __expf(m2 - m);
                smx[threadIdx.x] = m;
            }
            __syncthreads();
        }
        __shared__ float lp;
        if (threadIdx.x == 0) lp = smx[0] + __logf(ss[0]);
        __syncthreads();
        for (int m = threadIdx.x; m < NN; m += TPB)
            d_piadj[m] = pri[m] - lp - d_rowmax[m];
    }
}

__global__ void k_gather(const float* __restrict__ emis, const int* __restrict__ x) {
    int t = blockIdx.x;
    __shared__ int tok[BB];
    if (threadIdx.x < BB) tok[threadIdx.x] = x[threadIdx.x * TT + t];
    __syncthreads();
    float* dst = d_emitg + (size_t)t * NN * BB;
    for (int i = threadIdx.x; i < NN * BB; i += TPB) {
        int m = i >> 4, b = i & 15;
        dst[i] = __ldg(&emis[(size_t)m * VV + tok[b]]) - d_rowlse[m] + d_rowmax[m];
    }
}

// ---------------- persistent forward recursion ----------------
// smem: E bf16 16KB + ea bf16 32KB + alpha partials (2x128) + ea temp (128)
#define FWD_SMEM (RR*NN*2 + BB*NN*2 + (2*RR*BB + RR*BB)*4)

__global__ void __launch_bounds__(TPB, 1)
k_forward(const int* __restrict__ len, float* __restrict__ out) {
    extern __shared__ char sh[];
    char*  E_shb    = sh;                            // [RR][NN] bf16, 16KB
    char*  ea_sh    = sh + RR * NN * 2;              // [BB][NN] bf16, 32KB
    float* alpha_sh = (float*)(ea_sh + BB * NN * 2); // [2][RR*BB] partials
    float* eat_sh   = alpha_sh + 2 * RR * BB;        // [RR*BB]
    __shared__ float sA[BB], sB[BB];                 // shift(t-1), shift(t)

    const int g = blockIdx.x, tid = threadIdx.x;
    const int w = tid >> 5, lane = tid & 31;
    const int nh = w >> 2;                 // n-half: warps 0-3 -> 0, 4-7 -> 1
    const int mt = w & 1, bt = (w >> 1) & 1;
    const int ltid = tid & 127;
    const unsigned ea_smem = (unsigned)__cvta_generic_to_shared(ea_sh);

    // stage E_T slice (bf16, 16KB) once
    {
        const uint4* src = (const uint4*)(d_ETh + (size_t)g * RR * NN);
        uint4* dst = (uint4*)E_shb;
        for (int i = tid; i < RR * NN * 2 / 16; i += TPB) dst[i] = src[i];
    }
    if (tid < BB) { sA[tid] = 0.f; sB[tid] = 0.f; }
    float lseP = 0.f, sPrev = 0.f;                   // tid<16 state
    __syncthreads();

    const int ml_f = tid >> 4, b_f = tid & 15, m_f = g * RR + ml_f;

    for (int t = 0; t < TT; t++) {
        // prefetches: emit term + easum(t-1) (final since barrier t-1)
        float em = 0.f, pa = 0.f, easumP = 0.f;
        if (tid < RR * BB) {
            em = __ldcg(&d_emitg[((size_t)t * NN + m_f) * BB + b_f]);
            if (t == 0) pa = __ldcg(&d_piadj[m_f]);
        }
        if (tid < BB && t > 0)
            easumP = __ldcg(&d_easum[(t - 1) * BB + tid]);

        // -------- matvec: 2 chunks per n-half, per-half barrier pipeline ----
        if (t > 0) {
            unsigned long long acc[4][8];
#pragma unroll
            for (int j = 0; j < 4; j++)
#pragma unroll
                for (int k = 0; k < 8; k++) acc[j][k] = 0ull;
#pragma unroll
            for (int cc = 0; cc < 2; cc++) {
                if (cc == 0) asm volatile("cp.async.wait_group 1;");
                else         asm volatile("cp.async.wait_group 0;");
                asm volatile("bar.sync %0, 128;" :: "r"(2 + nh));
                int n0 = nh * 512 + cc * 256 + lane * 8;   // 8 bf16 per lane
                uint4 ev[4];
#pragma unroll
                for (int j = 0; j < 4; j++)
                    ev[j] = *(const uint4*)(E_shb + ((mt * 4 + j) * NN + n0) * 2);
                unsigned long long e[4][4];
#pragma unroll
                for (int j = 0; j < 4; j++) {
                    e[j][0] = bf2f32x2(ev[j].x); e[j][1] = bf2f32x2(ev[j].y);
                    e[j][2] = bf2f32x2(ev[j].z); e[j][3] = bf2f32x2(ev[j].w);
                }
#pragma unroll
                for (int k = 0; k < 8; k++) {
                    uint4 av = *(const uint4*)(ea_sh + ((bt * 8 + k) * NN + n0) * 2);
                    unsigned long long a0 = bf2f32x2(av.x), a1 = bf2f32x2(av.y);
                    unsigned long long a2 = bf2f32x2(av.z), a3 = bf2f32x2(av.w);
#pragma unroll
                    for (int j = 0; j < 4; j++) {
                        acc[j][k] = ffma2(e[j][0], a0, acc[j][k]);
                        acc[j][k] = ffma2(e[j][1], a1, acc[j][k]);
                        acc[j][k] = ffma2(e[j][2], a2, acc[j][k]);
                        acc[j][k] = ffma2(e[j][3], a3, acc[j][k]);
                    }
                }
            }
            float r[4][8];
#pragma unroll
            for (int j = 0; j < 4; j++)
#pragma unroll
                for (int k = 0; k < 8; k++) {
                    float2 f = *(float2*)&acc[j][k];
                    r[j][k] = f.x + f.y;
                }
#pragma unroll
            for (int off = 16; off; off >>= 1)
#pragma unroll
                for (int j = 0; j < 4; j++)
#pragma unroll
                    for (int k = 0; k < 8; k++)
                        r[j][k] += __shfl_xor_sync(0xffffffffu, r[j][k], off);
            if (lane == 0) {
#pragma unroll
                for (int j = 0; j < 4; j++)
#pragma unroll
                    for (int k = 0; k < 8; k++)
                        alpha_sh[nh * 128 + (mt * 4 + j) * BB + bt * 8 + k] = r[j][k];
            }
        }

        // -------- shift(t) from lse(t-1) (pre-barrier, prefetched easum) ----
        if (tid < BB) {
            float sh_t;
            if (t == 0) sh_t = 0.f;
            else {
                float lse = sPrev + __logf(easumP);          // lse(t-1)
                float d = (t == 1) ? 0.f
                                   : fminf(20.f, fmaxf(-40.f, lse - lseP));
                sh_t = lse + d;
                lseP = lse;
            }
            sA[tid] = sPrev;
            sB[tid] = sh_t;
            sPrev = sh_t;
            if (g == 0) d_shift[t * BB + tid] = sh_t;
        }
        __syncthreads();

        // -------- finalize: alpha -> ea (shifted) --------
        if (tid < RR * BB) {
            float A = (t == 0)
                ? (em + pa)
                : (em + sA[b_f] + __logf(alpha_sh[tid] + alpha_sh[128 + tid]));
            eat_sh[tid] = __expf(A - sB[b_f]);
        }
        __syncthreads();

        // pack bf16 pairs -> d_eag[t&1]
        if (tid < 64) {
            int b = tid >> 2, q = tid & 3;
            float e0 = eat_sh[(2 * q) * BB + b];
            float e1 = eat_sh[(2 * q + 1) * BB + b];
            unsigned* dst = (unsigned*)&d_eag[t & 1][b * NN + g * RR + 2 * q];
            *dst = bf16x2pack(e0, e1);
        }
        // per-batch partial sums -> global
        if (tid < BB) {
            float sm = eat_sh[tid];
#pragma unroll
            for (int ml = 1; ml < RR; ml++) sm += eat_sh[ml * BB + tid];
            atomicAdd(&d_easum[t * BB + tid], sm);
        }

        gbar((unsigned)(t + 1) * GG);

        // -------- issue async reload of ea(t) for step t+1 (per half) ------
        if (t < TT - 1) {
            const char* src = (const char*)d_eag[t & 1];
#pragma unroll
            for (int cc = 0; cc < 2; cc++) {
#pragma unroll
                for (int k = 0; k < 4; k++) {
                    int idx = ltid + 128 * k;        // [0,512) 16B units
                    int b = idx >> 5, o = idx & 31;
                    unsigned off =
                        (unsigned)(b * (NN * 2) + nh * 1024 + cc * 512 + o * 16);
                    cp_async16(ea_smem + off, src + off);
                }
                asm volatile("cp.async.commit_group;");
            }
        }
    }

    // final output: out[b] = shift[len-1] + log(easum[len-1])
    if (g == 0 && tid < BB) {
        int tb = len[tid] - 1;
        tb = tb < 0 ? 0 : (tb > TT - 1 ? TT - 1 : tb);
        out[tid] = d_shift[tb * BB + tid] + __logf(__ldcg(&d_easum[tb * BB + tid]));
    }
}

// ---------------- launch ----------------
extern "C" void kernel_launch(void* const* d_in, const int* in_sizes, int n_in,
                              void* d_out, int out_size) {
    (void)in_sizes; (void)n_in; (void)out_size;
    const float* emis  = (const float*)d_in[0];  // (N, V)
    const float* trans = (const float*)d_in[1];  // (N, N)
    const float* pri   = (const float*)d_in[2];  // (N,)
    const int*   x     = (const int*)d_in[3];    // (B, T)
    const int*   len   = (const int*)d_in[4];    // (B,)
    float*       out   = (float*)d_out;          // (B, 1)

    cudaFuncSetAttribute(k_forward, cudaFuncAttributeMaxDynamicSharedMemorySize,
                         FWD_SMEM);

    k_rowlse<<<NN, TPB>>>(emis);
    k_collse<<<NN / 32, dim3(32, 8)>>>(trans);
    k_prepT<<<NN, TPB>>>(trans);
    k_init<<<16, TPB>>>(pri);
    k_gather<<<TT, TPB>>>(emis, x);
    k_forward<<<GG, TPB, FWD_SMEM>>>(len, out);
}